// round 16
// baseline (speedup 1.0000x reference)
#include <cuda_runtime.h>
#include <cuda_bf16.h>
#include <cstdint>

// Problem constants
#define BS      16
#define C_TOT   512
#define HW      1024
#define N_TOT   16384
#define M_SUB   8
#define NE      1024
#define E_DIM   64

// Tiling
#define TM      128            // z rows per CTA
#define KC      64             // codes per chunk (tensor kernel)
#define NCH     (NE / KC)      // 16
#define MARGIN  5e-5f          // >= worst-case cross-scale ordering discrepancy

// Output layout (float32, tuple-concatenated)
#define OUT_LOSS 8388608
#define OUT_IDX  8388609
#define OUT_BIN  (OUT_IDX + M_SUB * N_TOT)

// Scratch (static; no cudaMalloc allowed)
__device__ int   g_idx[M_SUB * N_TOT];
__device__ float g_rowdist[M_SUB * N_TOT];       // dist' = en - 2*dot (no zn)
__device__ int   g_bins[NE];
__device__ int   g_fbcnt[M_SUB];
__device__ int   g_fblist[M_SUB][N_TOT];
__device__ unsigned long long g_fbkey[M_SUB * N_TOT];
__device__ float g_zpart[1024];                  // per-(m,tile): sum z^2 + sum dist'
// pre-split codebook: [m*NE + code][split(2)][32 words of bf16x2]
__device__ __align__(16) uint32_t g_cbsplit[M_SUB * NE * 64];
__device__ __align__(16) float    g_en[M_SUB * NE];

// ---- tensor-kernel smem word map (u32 units) ----
// zsh (A staging): words 0..9215.  Three B ring-bufs DISJOINT at 9216+s*4608.
// en: [3][64] floats at 23040.  One barrier per chunk is then sufficient.
#define W_BUF0 9216
#define W_EN   23040
#define SMEM_WORDS 23232
#define SMEM_BYTES (SMEM_WORDS * 4)   // 92928 B -> 2 CTAs/SM (185856 < 228K)

__device__ __forceinline__ void cp_async16(uint32_t saddr, const void* gptr) {
    asm volatile("cp.async.cg.shared.global [%0], [%1], 16;" :: "r"(saddr), "l"(gptr));
}
#define CP_COMMIT() asm volatile("cp.async.commit_group;")
#define CP_WAIT(n)  asm volatile("cp.async.wait_group %0;" :: "n"(n))

__device__ __forceinline__ void mma_bf16(float* c, const uint32_t* a,
                                         uint32_t b0, uint32_t b1) {
    asm volatile(
        "mma.sync.aligned.m16n8k16.row.col.f32.bf16.bf16.f32 "
        "{%0,%1,%2,%3}, {%4,%5,%6,%7}, {%8,%9}, {%0,%1,%2,%3};"
        : "+f"(c[0]), "+f"(c[1]), "+f"(c[2]), "+f"(c[3])
        : "r"(a[0]), "r"(a[1]), "r"(a[2]), "r"(a[3]), "r"(b0), "r"(b1));
}

__device__ __forceinline__ uint32_t pack2(float a, float b) {
    __nv_bfloat162 t = __floats2bfloat162_rn(a, b);
    return *reinterpret_cast<uint32_t*>(&t);
}
__device__ __forceinline__ void split1(float v, float& hi, float& lo) {
    __nv_bfloat16 h = __float2bfloat16_rn(v);
    hi = __bfloat162float(h);
    lo = v - hi;                       // exact in fp32
}

// ---------------------------------------------------------------------------
__global__ void vq_init_kernel() {
    int t = blockIdx.x * 256 + threadIdx.x;
    if (t < NE) g_bins[t] = 0;
    if (t >= NE && t < NE + M_SUB) g_fbcnt[t - NE] = 0;
}

// ---------------------------------------------------------------------------
// Precompute: split codebook to bf16 hi/lo planes (mma-ready layout) + ||e||^2.
// ---------------------------------------------------------------------------
__global__ __launch_bounds__(256)
void vq_precompute_kernel(const float* __restrict__ cb)
{
    int t = blockIdx.x * 256 + threadIdx.x;      // 8192 codes total
    if (t >= M_SUB * NE) return;
    const float4* src = reinterpret_cast<const float4*>(cb + (size_t)t * E_DIM);
    uint32_t* dst = g_cbsplit + (size_t)t * 64;  // [split][32w]
    float en = 0.f;
    #pragma unroll
    for (int q = 0; q < 16; q++) {
        float4 v = src[q];
        en += v.x * v.x + v.y * v.y + v.z * v.z + v.w * v.w;
        float hx, lx, hy, ly, hz, lz, hw_, lw_;
        split1(v.x, hx, lx); split1(v.y, hy, ly);
        split1(v.z, hz, lz); split1(v.w, hw_, lw_);
        dst[q * 2]          = pack2(hx, hy);
        dst[q * 2 + 1]      = pack2(hz, hw_);
        dst[32 + q * 2]     = pack2(lx, ly);
        dst[32 + q * 2 + 1] = pack2(lz, lw_);
    }
    g_en[t] = en;
}

// ---------------------------------------------------------------------------
// Tensor kernel: bf16-split mma.sync (3 products), per-row argmin on
// dist' = en - 2*dot with second-min MARGIN flagging. 3-stage cp.async ring
// over disjoint bufs -> ONE barrier per chunk (the iter-ch barrier protects
// buf (ch-1)%3 == (ch+2)%3 before refill). Ascending per-thread code order
// + strict < => lowest-index ties; cross-lane merges tie-break explicitly.
// ---------------------------------------------------------------------------
__global__ __launch_bounds__(256, 2)
void vq_tensor_kernel(const float* __restrict__ z)
{
    extern __shared__ __align__(16) uint32_t sm[];
    float* smf = reinterpret_cast<float*>(sm);
    __nv_bfloat16* smh = reinterpret_cast<__nv_bfloat16*>(sm);

    const int tid = threadIdx.x;
    const int w = tid >> 5, lane = tid & 31, g = lane >> 2, tg = lane & 3;
    const int m = blockIdx.y, tile = blockIdx.x;
    const int n_base = tile * TM, b = n_base >> 10, hw0 = n_base & 1023;

    const uint32_t sbase = (uint32_t)__cvta_generic_to_shared(sm);

    auto prefetch = [&](int ch, int s) {
        const uint32_t bw = W_BUF0 + (uint32_t)s * 4608u;
        const uint32_t* src = g_cbsplit + ((size_t)m * NE + ch * KC) * 64;
        #pragma unroll
        for (int q = 0; q < 4; q++) {
            int idx = q * 256 + tid;                 // 0..1023
            int split = idx >> 9, code = (idx >> 3) & 63, p = idx & 7;
            uint32_t dw = bw + split * 2304 + code * 36 + p * 4;
            cp_async16(sbase + dw * 4, src + (size_t)code * 64 + split * 32 + p * 4);
        }
        if (tid < 16)
            cp_async16(sbase + (W_EN + s * 64 + tid * 4) * 4,
                       g_en + m * NE + ch * KC + tid * 4);
        CP_COMMIT();
    };

    prefetch(0, 0);
    prefetch(1, 1);

    // stage A: split z rows into bf16 hi/lo planes at words 0..9215
    {
        const int row = tid & 127, h = tid >> 7;
        const float* zsrc = z + (size_t)(b * C_TOT + m * E_DIM) * HW + hw0;
        #pragma unroll
        for (int i = 0; i < 32; i++) {
            int d = h + 2 * i;
            float v = zsrc[(size_t)d * HW + row];
            float hi, lo; split1(v, hi, lo);
            smh[row * 72 + d]        = __float2bfloat16_rn(hi);
            smh[9216 + row * 72 + d] = __float2bfloat16_rn(lo);
        }
    }
    __syncthreads();

    // A fragments -> registers (reused for all 16 chunks; zsh stays intact)
    const int r0 = w * 16 + g;
    uint32_t af[2][4][4];
    #pragma unroll
    for (int s = 0; s < 2; s++)
        #pragma unroll
        for (int ks = 0; ks < 4; ks++) {
            int base = s * 4608 + ks * 8 + tg;
            af[s][ks][0] = sm[base + r0 * 36];
            af[s][ks][1] = sm[base + (r0 + 8) * 36];
            af[s][ks][2] = sm[base + r0 * 36 + 4];
            af[s][ks][3] = sm[base + (r0 + 8) * 36 + 4];
        }

    float b1v0 = 3.4e38f, b2v0 = 3.4e38f, b1v1 = 3.4e38f, b2v1 = 3.4e38f;
    int   bi0 = 0, bi1 = 0;
    const int boff = g * 36 + tg;

    for (int ch = 0; ch < NCH; ch++) {
        const int s = ch % 3;
        const uint32_t bw = W_BUF0 + (uint32_t)s * 4608u;
        if (ch == NCH - 1) { CP_WAIT(0); } else { CP_WAIT(1); }
        __syncthreads();                 // buf[s]+en[s] ready; (ch-1)%3 free
        if (ch + 2 < NCH) prefetch(ch + 2, (ch + 2) % 3);

        float acc[8][4];
        #pragma unroll
        for (int nt = 0; nt < 8; nt++)
            acc[nt][0] = acc[nt][1] = acc[nt][2] = acc[nt][3] = 0.f;

        #pragma unroll
        for (int ks = 0; ks < 4; ks++) {
            const int kb = bw + ks * 8 + boff;
            uint32_t bh[8][2];
            #pragma unroll
            for (int nt = 0; nt < 8; nt++) {
                bh[nt][0] = sm[kb + nt * 288];
                bh[nt][1] = sm[kb + nt * 288 + 4];
            }
            #pragma unroll
            for (int nt = 0; nt < 8; nt++)
                mma_bf16(acc[nt], af[0][ks], bh[nt][0], bh[nt][1]);
            #pragma unroll
            for (int nt = 0; nt < 8; nt++)
                mma_bf16(acc[nt], af[1][ks], bh[nt][0], bh[nt][1]);
            uint32_t bl[8][2];
            #pragma unroll
            for (int nt = 0; nt < 8; nt++) {
                bl[nt][0] = sm[kb + 2304 + nt * 288];
                bl[nt][1] = sm[kb + 2304 + nt * 288 + 4];
            }
            #pragma unroll
            for (int nt = 0; nt < 8; nt++)
                mma_bf16(acc[nt], af[0][ks], bl[nt][0], bl[nt][1]);
        }

        const float* enp = smf + W_EN + s * 64;
        #pragma unroll
        for (int nt = 0; nt < 8; nt++) {
            float en0 = enp[nt * 8 + tg * 2];
            float en1 = enp[nt * 8 + tg * 2 + 1];
            int k0 = ch * 64 + nt * 8 + tg * 2;
            float d00 = __fmaf_rn(-2.f, acc[nt][0], en0);
            float d01 = __fmaf_rn(-2.f, acc[nt][1], en1);
            float d10 = __fmaf_rn(-2.f, acc[nt][2], en0);
            float d11 = __fmaf_rn(-2.f, acc[nt][3], en1);
            if (d00 < b1v0) { b2v0 = b1v0; b1v0 = d00; bi0 = k0; }     else if (d00 < b2v0) b2v0 = d00;
            if (d01 < b1v0) { b2v0 = b1v0; b1v0 = d01; bi0 = k0 + 1; } else if (d01 < b2v0) b2v0 = d01;
            if (d10 < b1v1) { b2v1 = b1v1; b1v1 = d10; bi1 = k0; }     else if (d10 < b2v1) b2v1 = d10;
            if (d11 < b1v1) { b2v1 = b1v1; b1v1 = d11; bi1 = k0 + 1; } else if (d11 < b2v1) b2v1 = d11;
        }
    }

    // quad reduce (lanes tg 0..3 share rows r0 / r0+8); keeps true 2nd-min
    #pragma unroll
    for (int off = 1; off <= 2; off <<= 1) {
        float o1 = __shfl_xor_sync(0xffffffffu, b1v0, off);
        float o2 = __shfl_xor_sync(0xffffffffu, b2v0, off);
        int   oi = __shfl_xor_sync(0xffffffffu, bi0, off);
        if (o1 < b1v0 || (o1 == b1v0 && oi < bi0)) { b2v0 = fminf(b1v0, o2); b1v0 = o1; bi0 = oi; }
        else b2v0 = fminf(b2v0, o1);
        float p1 = __shfl_xor_sync(0xffffffffu, b1v1, off);
        float p2 = __shfl_xor_sync(0xffffffffu, b2v1, off);
        int   pi = __shfl_xor_sync(0xffffffffu, bi1, off);
        if (p1 < b1v1 || (p1 == b1v1 && pi < bi1)) { b2v1 = fminf(b1v1, p2); b1v1 = p1; bi1 = pi; }
        else b2v1 = fminf(b2v1, p1);
    }

    if (tg == 0) {
        int rr = m * N_TOT + n_base + r0;
        g_idx[rr] = bi0; g_rowdist[rr] = b1v0;
        if (b2v0 - b1v0 <= MARGIN) {
            g_fbkey[rr] = ~0ull;
            int p = atomicAdd(&g_fbcnt[m], 1); g_fblist[m][p] = n_base + r0;
        }
        rr += 8;
        g_idx[rr] = bi1; g_rowdist[rr] = b1v1;
        if (b2v1 - b1v1 <= MARGIN) {
            g_fbkey[rr] = ~0ull;
            int p = atomicAdd(&g_fbcnt[m], 1); g_fblist[m][p] = n_base + r0 + 8;
        }
    }
}

// ---------------------------------------------------------------------------
// Exact fallback v4, warp-per-row: block = (128-code chunk cx, row-group, m).
// Stage 128 codes at stride 65 (conflict-free column reads). Each warp owns a
// flagged row (z row in per-warp smem, broadcast reads); lane handles codes
// lane+32j (ascending => strict < keeps lowest index), 4 interleaved chains.
// Quantized dist fl(fl(zn+en) - 2*dot); identical code path per (row, code)
// in every block => bit-identical keys; cross-block argmin via atomicMin on
// (dist_bits<<32 | idx)  (dist > 0 => float bits order-monotone).
// ---------------------------------------------------------------------------
__global__ __launch_bounds__(128)
void vq_fallback_kernel(const float* __restrict__ z, const float* __restrict__ cb)
{
    __shared__ float sc[128][65];
    __shared__ float sen[128];
    __shared__ float zrow[4][64];
    const int tid = threadIdx.x;
    const int w = tid >> 5, lane = tid & 31;
    const int cx = blockIdx.x;            // code chunk 0..7 (128 codes each)
    const int m  = blockIdx.z;
    const int cnt = g_fbcnt[m];
    if ((int)blockIdx.y * 4 >= cnt) return;

    // stage 128 codes
    const float4* src = reinterpret_cast<const float4*>(
        cb + ((size_t)m * NE + cx * 128) * E_DIM);
    for (int i = tid; i < 128 * 16; i += 128) {
        int code = i >> 4, q = i & 15;
        float4 v = src[(size_t)code * 16 + q];
        sc[code][q * 4 + 0] = v.x;
        sc[code][q * 4 + 1] = v.y;
        sc[code][q * 4 + 2] = v.z;
        sc[code][q * 4 + 3] = v.w;
    }
    __syncthreads();
    if (tid < 128) {                      // en: same chain order everywhere
        float s = 0.f;
        const float* cr = sc[tid];
        #pragma unroll
        for (int d = 0; d < 64; d++) s = __fmaf_rn(cr[d], cr[d], s);
        sen[tid] = s;
    }
    __syncthreads();

    const int stride = 4 * gridDim.y;
    for (int i = blockIdx.y * 4 + w; i < cnt; i += stride) {
        int n = g_fblist[m][i];
        int r = m * N_TOT + n;
        int b = n >> 10, hw = n & 1023;
        const float* zp = z + (size_t)(b * C_TOT + m * E_DIM) * HW + hw;
        __syncwarp();                     // prior row's reads done
        zrow[w][lane]      = zp[(size_t)lane * HW];
        zrow[w][lane + 32] = zp[(size_t)(lane + 32) * HW];
        __syncwarp();

        float zn = 0.f;                   // identical chain in every block
        #pragma unroll
        for (int d = 0; d < 64; d++) zn = __fmaf_rn(zrow[w][d], zrow[w][d], zn);

        float dt0 = 0.f, dt1 = 0.f, dt2 = 0.f, dt3 = 0.f;
        const float* c0 = sc[lane];
        const float* c1 = sc[lane + 32];
        const float* c2 = sc[lane + 64];
        const float* c3 = sc[lane + 96];
        #pragma unroll
        for (int d = 0; d < 64; d++) {
            float zv = zrow[w][d];        // broadcast
            dt0 = __fmaf_rn(zv, c0[d], dt0);
            dt1 = __fmaf_rn(zv, c1[d], dt1);
            dt2 = __fmaf_rn(zv, c2[d], dt2);
            dt3 = __fmaf_rn(zv, c3[d], dt3);
        }
        float bv = 3.4e38f; int bc = 0;
        {
            float di;
            di = __fmaf_rn(-2.f, dt0, __fadd_rn(zn, sen[lane]));
            if (di < bv) { bv = di; bc = lane; }
            di = __fmaf_rn(-2.f, dt1, __fadd_rn(zn, sen[lane + 32]));
            if (di < bv) { bv = di; bc = lane + 32; }
            di = __fmaf_rn(-2.f, dt2, __fadd_rn(zn, sen[lane + 64]));
            if (di < bv) { bv = di; bc = lane + 64; }
            di = __fmaf_rn(-2.f, dt3, __fadd_rn(zn, sen[lane + 96]));
            if (di < bv) { bv = di; bc = lane + 96; }
        }
        // warp argmin with lowest-index ties
        #pragma unroll
        for (int off = 16; off >= 1; off >>= 1) {
            float ov = __shfl_xor_sync(0xffffffffu, bv, off);
            int   oc = __shfl_xor_sync(0xffffffffu, bc, off);
            if (ov < bv || (ov == bv && oc < bc)) { bv = ov; bc = oc; }
        }
        if (lane == 0) {
            unsigned long long key =
                ((unsigned long long)__float_as_uint(bv) << 32)
                | (unsigned)(cx * 128 + bc);
            atomicMin(&g_fbkey[r], key);
        }
    }
}

// ---------------------------------------------------------------------------
// Apply: decode winning keys into g_idx / g_rowdist (dist' convention).
// ---------------------------------------------------------------------------
__global__ __launch_bounds__(256)
void vq_apply_kernel(const float* __restrict__ z)
{
    const int m = blockIdx.y;
    const int cnt = g_fbcnt[m];
    for (int i = blockIdx.x * 256 + threadIdx.x; i < cnt; i += gridDim.x * 256) {
        int n = g_fblist[m][i];
        int r = m * N_TOT + n;
        unsigned long long key = g_fbkey[r];
        int   idx  = (int)(key & 0xFFFFFFFFull);
        float dist = __uint_as_float((unsigned)(key >> 32));
        int b = n >> 10, hw = n & 1023;
        const float* zp = z + (size_t)(b * C_TOT + m * E_DIM) * HW + hw;
        float zn = 0.f;
        #pragma unroll
        for (int d = 0; d < 64; d++) {
            float v = zp[(size_t)d * HW];
            zn = __fmaf_rn(v, v, zn);
        }
        g_idx[r] = idx;
        g_rowdist[r] = dist - zn;      // dist' convention
    }
}

// ---------------------------------------------------------------------------
// Scatter: gather chosen codes, straight-through rounding bit-exact
// (zq_st = fl(zf + fl(zq - zf))), float4 gmem both directions, histogram,
// + deterministic per-tile sum of (z^2 + dist') for the loss.
// ---------------------------------------------------------------------------
#define ZS_STRIDE 65
__global__ __launch_bounds__(256)
void vq_scatter_kernel(const float* __restrict__ z, const float* __restrict__ cb,
                       float* __restrict__ out)
{
    __shared__ float cs[TM][ZS_STRIDE];
    __shared__ int   sidx[TM];
    __shared__ float red[256];
    const int tid = threadIdx.x;
    const int m = blockIdx.y, tile = blockIdx.x;
    const int n_base = tile * TM, b = n_base >> 10, hw0 = n_base & 1023;

    if (tid < TM) {
        int v = g_idx[m * N_TOT + n_base + tid];
        sidx[tid] = v;
        atomicAdd(&g_bins[v], 1);
    }
    __syncthreads();
    const float4* cb4 = reinterpret_cast<const float4*>(cb + (size_t)m * NE * E_DIM);
    for (int idx4 = tid; idx4 < TM * 16; idx4 += 256) {
        int r = idx4 >> 4, d4 = idx4 & 15;
        float4 v = cb4[sidx[r] * 16 + d4];
        cs[r][d4 * 4 + 0] = v.x;
        cs[r][d4 * 4 + 1] = v.y;
        cs[r][d4 * 4 + 2] = v.z;
        cs[r][d4 * 4 + 3] = v.w;
    }
    __syncthreads();
    const float4* zsrc4 = reinterpret_cast<const float4*>(
        z + (size_t)(b * C_TOT + m * E_DIM) * HW + hw0);
    float4* dst4 = reinterpret_cast<float4*>(
        out + (size_t)(b * C_TOT + m * E_DIM) * HW + hw0);
    float zs = 0.f;
    #pragma unroll
    for (int it = 0; it < 8; it++) {
        int t = it * 256 + tid;               // 0..2047
        int d = t >> 5, n4 = t & 31;          // d row, 4-wide hw group
        float4 zv = zsrc4[(size_t)d * 256 + n4];
        zs += zv.x * zv.x + zv.y * zv.y + zv.z * zv.z + zv.w * zv.w;
        float4 ov;
        ov.x = __fadd_rn(zv.x, __fsub_rn(cs[n4 * 4 + 0][d], zv.x));
        ov.y = __fadd_rn(zv.y, __fsub_rn(cs[n4 * 4 + 1][d], zv.y));
        ov.z = __fadd_rn(zv.z, __fsub_rn(cs[n4 * 4 + 2][d], zv.z));
        ov.w = __fadd_rn(zv.w, __fsub_rn(cs[n4 * 4 + 3][d], zv.w));
        dst4[(size_t)d * 256 + n4] = ov;
    }
    if (tid < TM) zs += g_rowdist[m * N_TOT + n_base + tid];   // fold dist'
    red[tid] = zs;
    __syncthreads();
    for (int s = 128; s >= 1; s >>= 1) {
        if (tid < s) red[tid] += red[tid + s];
        __syncthreads();
    }
    if (tid == 0) g_zpart[m * 128 + tile] = red[0];
}

// ---------------------------------------------------------------------------
// Final: loss = (sum of per-tile partials) * 1.25/(N*64) + dtype conversions.
// ---------------------------------------------------------------------------
__global__ __launch_bounds__(256)
void vq_final_kernel(float* __restrict__ out)
{
    if (blockIdx.x == 0) {
        __shared__ float part[256];
        int tid = threadIdx.x;
        float s = 0.f;
        #pragma unroll
        for (int q = 0; q < 4; q++) s += g_zpart[tid * 4 + q];
        part[tid] = s;
        __syncthreads();
        if (tid == 0) {
            float t = 0.f;
            for (int q = 0; q < 256; q++) t += part[q];
            out[OUT_LOSS] = t * (1.25f / (float)(N_TOT * E_DIM));
        }
    } else {
        int off = (blockIdx.x - 1) * 256 + threadIdx.x;
        if (off < M_SUB * N_TOT) {
            out[OUT_IDX + off] = (float)g_idx[off];
        } else {
            int bo = off - M_SUB * N_TOT;
            if (bo < NE) out[OUT_BIN + bo] = (float)g_bins[bo];
        }
    }
}

// ---------------------------------------------------------------------------
extern "C" void kernel_launch(void* const* d_in, const int* in_sizes, int n_in,
                              void* d_out, int out_size)
{
    const float* z  = (const float*)d_in[0];
    const float* cb = (const float*)d_in[1];
    float* out = (float*)d_out;

    cudaFuncSetAttribute(vq_tensor_kernel,
                         cudaFuncAttributeMaxDynamicSharedMemorySize, SMEM_BYTES);

    vq_init_kernel<<<5, 256>>>();
    vq_precompute_kernel<<<32, 256>>>(cb);

    dim3 gridT(N_TOT / TM, M_SUB);            // 128 x 8
    vq_tensor_kernel<<<gridT, 256, SMEM_BYTES>>>(z);

    dim3 gridF(8, 8, M_SUB);                  // 128-code chunk x row-group x m
    vq_fallback_kernel<<<gridF, 128>>>(z, cb);

    dim3 gridA(4, M_SUB);
    vq_apply_kernel<<<gridA, 256>>>(z);

    dim3 gridS(N_TOT / TM, M_SUB);
    vq_scatter_kernel<<<gridS, 256>>>(z, cb, out);

    int conv_elems = M_SUB * N_TOT + NE;
    int gridC = 1 + (conv_elems + 255) / 256;
    vq_final_kernel<<<gridC, 256>>>(out);
}